// round 9
// baseline (speedup 1.0000x reference)
#include <cuda_runtime.h>
#include <cuda_bf16.h>
#include <cstdint>
#include <cstddef>

// Problem constants: B=2, S=2048, D_MODEL=1024, H=16, d_k=64
#define BATCH 2
#define SEQ 2048
#define DM 1024
#define NH 16
#define MROWS (BATCH * SEQ)   // 4096

// ---------------------------------------------------------------------------
// bf16 pool (element offsets)
// ---------------------------------------------------------------------------
#define SZ_ACT (4096ull * 1024ull)
#define SZ_W   (1024ull * 1024ull)
#define OFF_XQ_HI 0ull
#define OFF_XQ_LO (OFF_XQ_HI + SZ_ACT)
#define OFF_XK_HI (OFF_XQ_LO + SZ_ACT)
#define OFF_XK_LO (OFF_XK_HI + SZ_ACT)
#define OFF_XV_HI (OFF_XK_LO + SZ_ACT)
#define OFF_XV_LO (OFF_XV_HI + SZ_ACT)
#define OFF_WQ_HI (OFF_XV_LO + SZ_ACT)
#define OFF_WQ_LO (OFF_WQ_HI + SZ_W)
#define OFF_WK_HI (OFF_WQ_LO + SZ_W)
#define OFF_WK_LO (OFF_WK_HI + SZ_W)
#define OFF_WV_HI (OFF_WK_LO + SZ_W)
#define OFF_WV_LO (OFF_WV_HI + SZ_W)
#define OFF_WO_HI (OFF_WV_LO + SZ_W)
#define OFF_WO_LO (OFF_WO_HI + SZ_W)
#define OFF_CTX_HI (OFF_WO_LO + SZ_W)
#define OFF_CTX_LO (OFF_CTX_HI + SZ_ACT)
// head-major attention operands: [b*16+h][s][64]
#define OFF_AQ_HI (OFF_CTX_LO + SZ_ACT)
#define OFF_AQ_LO (OFF_AQ_HI + SZ_ACT)
#define OFF_AK_HI (OFF_AQ_LO + SZ_ACT)
#define OFF_AK_LO (OFF_AK_HI + SZ_ACT)
#define OFF_AV_HI (OFF_AK_LO + SZ_ACT)
#define OFF_AV_LO (OFF_AV_HI + SZ_ACT)
#define BF_TOTAL  (OFF_AV_LO + SZ_ACT)
__device__ __nv_bfloat16 g_bf[BF_TOTAL];

// ---------------------------------------------------------------------------
// PTX helpers — baseline ISA only (cp.async / ldmatrix / mma.sync / cvt)
// ---------------------------------------------------------------------------
__device__ __forceinline__ uint32_t smem_u32(const void* p) {
    uint32_t a;
    asm("{ .reg .u64 t; cvta.to.shared.u64 t, %1; cvt.u32.u64 %0, t; }"
        : "=r"(a) : "l"(p));
    return a;
}

#define CP_ASYNC16(dst, src) \
    asm volatile("cp.async.cg.shared.global [%0], [%1], 16;" :: "r"(dst), "l"(src))
#define CP_COMMIT() asm volatile("cp.async.commit_group;" ::: "memory")
#define CP_WAIT(N)  asm volatile("cp.async.wait_group %0;" :: "n"(N) : "memory")

#define LDSM4(R, addr) \
    asm volatile("ldmatrix.sync.aligned.m8n8.x4.shared.b16 {%0,%1,%2,%3}, [%4];" \
        : "=r"((R)[0]), "=r"((R)[1]), "=r"((R)[2]), "=r"((R)[3]) : "r"(addr))
#define LDSM4T(R, addr) \
    asm volatile("ldmatrix.sync.aligned.m8n8.x4.trans.shared.b16 {%0,%1,%2,%3}, [%4];" \
        : "=r"((R)[0]), "=r"((R)[1]), "=r"((R)[2]), "=r"((R)[3]) : "r"(addr))

#define MMA16816(C, A, b0, b1) \
    asm volatile("mma.sync.aligned.m16n8k16.row.col.f32.bf16.bf16.f32 " \
        "{%0,%1,%2,%3}, {%4,%5,%6,%7}, {%8,%9}, {%0,%1,%2,%3};" \
        : "+f"((C)[0]), "+f"((C)[1]), "+f"((C)[2]), "+f"((C)[3]) \
        : "r"((A)[0]), "r"((A)[1]), "r"((A)[2]), "r"((A)[3]), "r"(b0), "r"(b1))

__device__ __forceinline__ float ex2(float x) {
    float r; asm("ex2.approx.ftz.f32 %0, %1;" : "=f"(r) : "f"(x)); return r;
}
__device__ __forceinline__ uint32_t packbf(float lo, float hi) {
    uint32_t u;
    asm("cvt.rn.bf16x2.f32 %0, %1, %2;" : "=r"(u) : "f"(hi), "f"(lo));
    return u;
}
__device__ __forceinline__ float bflo(uint32_t u) { return __uint_as_float(u << 16); }
__device__ __forceinline__ float bfhi(uint32_t u) { return __uint_as_float(u & 0xffff0000u); }

__device__ __forceinline__ void split_store2(
    __nv_bfloat16* hp, __nv_bfloat16* lp, size_t idx, float a, float b)
{
    __nv_bfloat16 ha = __float2bfloat16(a);
    __nv_bfloat16 hb = __float2bfloat16(b);
    __nv_bfloat16 la = __float2bfloat16(a - __bfloat162float(ha));
    __nv_bfloat16 lb = __float2bfloat16(b - __bfloat162float(hb));
    *reinterpret_cast<__nv_bfloat162*>(hp + idx) = __nv_bfloat162(ha, hb);
    *reinterpret_cast<__nv_bfloat162*>(lp + idx) = __nv_bfloat162(la, lb);
}

// ---------------------------------------------------------------------------
// ONE merged fp32 -> bf16 hi/lo split conversion for all 7 tensors.
// ---------------------------------------------------------------------------
__global__ __launch_bounds__(256) void convert_all(
    const float* __restrict__ q, const float* __restrict__ k,
    const float* __restrict__ v, const float* __restrict__ wq,
    const float* __restrict__ wk, const float* __restrict__ wv,
    const float* __restrict__ wo)
{
    const int blk = blockIdx.x;
    const float* src;
    size_t hiOff, loOff, base;
    if (blk < 12288) {
        int t = blk >> 12;
        src = (t == 0) ? q : (t == 1) ? k : v;
        hiOff = (t == 0) ? OFF_XQ_HI : (t == 1) ? OFF_XK_HI : OFF_XV_HI;
        loOff = (t == 0) ? OFF_XQ_LO : (t == 1) ? OFF_XK_LO : OFF_XV_LO;
        base = ((size_t)(blk & 4095)) << 10;
    } else {
        int t = (blk - 12288) >> 10;
        src = (t == 0) ? wq : (t == 1) ? wk : (t == 2) ? wv : wo;
        hiOff = (t == 0) ? OFF_WQ_HI : (t == 1) ? OFF_WK_HI
              : (t == 2) ? OFF_WV_HI : OFF_WO_HI;
        loOff = (t == 0) ? OFF_WQ_LO : (t == 1) ? OFF_WK_LO
              : (t == 2) ? OFF_WV_LO : OFF_WO_LO;
        base = ((size_t)((blk - 12288) & 1023)) << 10;
    }
    size_t i = base + (size_t)threadIdx.x * 4;
    float4 x = *(const float4*)(src + i);
    __nv_bfloat16 h[4], l[4];
    float vv[4] = {x.x, x.y, x.z, x.w};
#pragma unroll
    for (int j = 0; j < 4; j++) {
        h[j] = __float2bfloat16(vv[j]);
        l[j] = __float2bfloat16(vv[j] - __bfloat162float(h[j]));
    }
    *reinterpret_cast<__nv_bfloat162*>(g_bf + hiOff + i)     = __nv_bfloat162(h[0], h[1]);
    *reinterpret_cast<__nv_bfloat162*>(g_bf + hiOff + i + 2) = __nv_bfloat162(h[2], h[3]);
    *reinterpret_cast<__nv_bfloat162*>(g_bf + loOff + i)     = __nv_bfloat162(l[0], l[1]);
    *reinterpret_cast<__nv_bfloat162*>(g_bf + loOff + i + 2) = __nv_bfloat162(l[2], l[3]);
}

// ---------------------------------------------------------------------------
// GEMM core: 512 threads, 4x4 warp grid, 32x32 warp tiles, CTA tile 128x128.
// ---------------------------------------------------------------------------
#define NT 32
#define KT 32
#define ROWB 80
#define TILEB (128 * ROWB)
#define STAGEB (4 * TILEB)
#define GEMM_SMEM (2 * STAGEB)

__device__ __forceinline__ void gemm_core512(
    uint32_t sbase, size_t aHi, size_t aLo, size_t bHi, size_t bLo,
    int m0, int n0, float A[2][4][4])
{
    const int tid  = threadIdx.x;
    const int lane = tid & 31;
    const int wid  = tid >> 5;          // 0..15

    const __nv_bfloat16* gp0 = g_bf + aHi + (size_t)m0 * 1024;
    const __nv_bfloat16* gp1 = g_bf + aLo + (size_t)m0 * 1024;
    const __nv_bfloat16* gp2 = g_bf + bHi + (size_t)n0 * 1024;
    const __nv_bfloat16* gp3 = g_bf + bLo + (size_t)n0 * 1024;

    // 2048 16B chunks, 512 threads -> 4 per thread (one per tile)
    auto issue = [&](int kt, int stage) {
        const int kc = kt * KT;
#pragma unroll
        for (int j = 0; j < 4; j++) {
            int c  = tid + j * 512;
            int r  = (c >> 2) & 127;
            int qq = c & 3;
            uint32_t dst = sbase + stage * STAGEB + j * TILEB + r * ROWB + qq * 16;
            const __nv_bfloat16* base =
                (j == 0) ? gp0 : (j == 1) ? gp1 : (j == 2) ? gp2 : gp3;
            CP_ASYNC16(dst, base + (size_t)r * 1024 + kc + qq * 8);
        }
        CP_COMMIT();
    };

    issue(0, 0);
    issue(1, 1);

    const int wm = wid & 3;             // 4 M rows of warps
    const int wn = wid >> 2;            // 4 N cols of warps
    const int a_row  = (lane & 7) + ((lane >> 3) & 1) * 8;
    const int a_colb = ((lane >> 4) * 8) * 2;
    const int b_row  = (lane & 7) + ((lane >> 4)) * 8;
    const int b_colb = (((lane >> 3) & 1) * 8) * 2;

#pragma unroll
    for (int i = 0; i < 2; i++)
#pragma unroll
        for (int j = 0; j < 4; j++)
#pragma unroll
            for (int e = 0; e < 4; e++) A[i][j][e] = 0.f;

    for (int kt = 0; kt < NT; kt++) {
        if (kt == NT - 1) CP_WAIT(0); else CP_WAIT(1);
        __syncthreads();
        const uint32_t st = sbase + (kt & 1) * STAGEB;

#pragma unroll
        for (int ks = 0; ks < 2; ks++) {
            uint32_t aH[2][4], aL[2][4];
#pragma unroll
            for (int i = 0; i < 2; i++) {
                uint32_t ad = st + (wm * 32 + i * 16 + a_row) * ROWB + ks * 32 + a_colb;
                LDSM4(aH[i], ad);
                LDSM4(aL[i], ad + TILEB);
            }
            uint32_t bH[2][4], bL[2][4];
#pragma unroll
            for (int j = 0; j < 2; j++) {
                uint32_t bd = st + 2 * TILEB +
                              (wn * 32 + j * 16 + b_row) * ROWB + ks * 32 + b_colb;
                LDSM4(bH[j], bd);
                LDSM4(bL[j], bd + TILEB);
            }
#pragma unroll
            for (int i = 0; i < 2; i++) {
#pragma unroll
                for (int jf = 0; jf < 4; jf++) {
                    uint32_t h0 = bH[jf >> 1][(jf & 1) * 2];
                    uint32_t h1 = bH[jf >> 1][(jf & 1) * 2 + 1];
                    uint32_t l0 = bL[jf >> 1][(jf & 1) * 2];
                    uint32_t l1 = bL[jf >> 1][(jf & 1) * 2 + 1];
                    MMA16816(A[i][jf], aH[i], h0, h1);
                    MMA16816(A[i][jf], aH[i], l0, l1);
                    MMA16816(A[i][jf], aL[i], h0, h1);
                }
            }
        }
        __syncthreads();
        if (kt + 2 < NT) issue(kt + 2, kt & 1);
    }
}

// QKV projections merged into one launch: blockIdx.z in {0,1,2}
__global__ __launch_bounds__(512) void gemm_qkv(
    const float* __restrict__ bq, const float* __restrict__ bk,
    const float* __restrict__ bv)
{
    extern __shared__ char sm[];
    const uint32_t sbase = smem_u32(sm);
    const int lane = threadIdx.x & 31;
    const int wid  = threadIdx.x >> 5;
    const int m0 = blockIdx.y << 7;
    const int n0 = blockIdx.x << 7;
    const int z  = blockIdx.z;

    size_t aHi, aLo, bHi, bLo, dH, dL;
    const float* bias;
    if (z == 0) { aHi = OFF_XQ_HI; aLo = OFF_XQ_LO; bHi = OFF_WQ_HI; bLo = OFF_WQ_LO;
                  dH = OFF_AQ_HI; dL = OFF_AQ_LO; bias = bq; }
    else if (z == 1) { aHi = OFF_XK_HI; aLo = OFF_XK_LO; bHi = OFF_WK_HI; bLo = OFF_WK_LO;
                  dH = OFF_AK_HI; dL = OFF_AK_LO; bias = bk; }
    else { aHi = OFF_XV_HI; aLo = OFF_XV_LO; bHi = OFF_WV_HI; bLo = OFF_WV_LO;
                  dH = OFF_AV_HI; dL = OFF_AV_LO; bias = bv; }

    float A[2][4][4];
    gemm_core512(sbase, aHi, aLo, bHi, bLo, m0, n0, A);

    const int mrb = m0 + (wid & 3) * 32;
    const int ncb = n0 + (wid >> 2) * 32;
    __nv_bfloat16* hp = g_bf + dH;
    __nv_bfloat16* lp = g_bf + dL;
#pragma unroll
    for (int i = 0; i < 2; i++) {
        int r0 = mrb + i * 16 + (lane >> 2);
#pragma unroll
        for (int jf = 0; jf < 4; jf++) {
            int c = ncb + jf * 8 + (lane & 3) * 2;
            float bx = __ldg(bias + c);
            float by = __ldg(bias + c + 1);
            int h = c >> 6, d = c & 63;
            size_t ix0 = ((size_t)(((r0 >> 11) << 4) | h) << 17)
                       + ((size_t)(r0 & 2047) << 6) + d;
            split_store2(hp, lp, ix0, A[i][jf][0] + bx, A[i][jf][1] + by);
            split_store2(hp, lp, ix0 + (8ull << 6), A[i][jf][2] + bx, A[i][jf][3] + by);
        }
    }
}

// Output projection: ctx (split bf16) x Wo^T + bo -> fp32 out
__global__ __launch_bounds__(512) void gemm_out(
    const float* __restrict__ bias, float* __restrict__ ext)
{
    extern __shared__ char sm[];
    const uint32_t sbase = smem_u32(sm);
    const int lane = threadIdx.x & 31;
    const int wid  = threadIdx.x >> 5;
    const int m0 = blockIdx.y << 7;
    const int n0 = blockIdx.x << 7;

    float A[2][4][4];
    gemm_core512(sbase, OFF_CTX_HI, OFF_CTX_LO, OFF_WO_HI, OFF_WO_LO, m0, n0, A);

    const int mrb = m0 + (wid & 3) * 32;
    const int ncb = n0 + (wid >> 2) * 32;
#pragma unroll
    for (int i = 0; i < 2; i++) {
        int r0 = mrb + i * 16 + (lane >> 2);
#pragma unroll
        for (int jf = 0; jf < 4; jf++) {
            int cb = ncb + jf * 8 + (lane & 3) * 2;
            float bx = __ldg(bias + cb);
            float by = __ldg(bias + cb + 1);
            float2 o0 = make_float2(A[i][jf][0] + bx, A[i][jf][1] + by);
            float2 o1 = make_float2(A[i][jf][2] + bx, A[i][jf][3] + by);
            *reinterpret_cast<float2*>(ext + (size_t)r0 * 1024 + cb)       = o0;
            *reinterpret_cast<float2*>(ext + (size_t)(r0 + 8) * 1024 + cb) = o1;
        }
    }
}

// ---------------------------------------------------------------------------
// Tensor-core flash attention (split-bf16, fixed-scale softmax).
// CTA: 128 queries x one (b,h). 8 warps x 16-q tiles. Key tiles of 64.
// 3-stage cp.async pipeline (wait ladder 2/1/0).
// ---------------------------------------------------------------------------
#define ATT_STAGE 32768            // KH 8K | KL 8K | VH 8K | VL 8K
#define ATT_NSTG  3
#define ATT_SMEM  (ATT_NSTG * ATT_STAGE)  // 96 KB

__global__ __launch_bounds__(256, 2) void attn_tc()
{
    extern __shared__ char sm[];
    const uint32_t sb = smem_u32(sm);
    const int tid = threadIdx.x, lane = tid & 31, wid = tid >> 5;
    const int bh = blockIdx.y;
    const int q0 = blockIdx.x << 7;

    const __nv_bfloat16* Qh = g_bf + OFF_AQ_HI + ((size_t)bh << 17) + ((size_t)q0 << 6);
    const __nv_bfloat16* Ql = g_bf + OFF_AQ_LO + ((size_t)bh << 17) + ((size_t)q0 << 6);
    const __nv_bfloat16* Kh = g_bf + OFF_AK_HI + ((size_t)bh << 17);
    const __nv_bfloat16* Kl = g_bf + OFF_AK_LO + ((size_t)bh << 17);
    const __nv_bfloat16* Vh = g_bf + OFF_AV_HI + ((size_t)bh << 17);
    const __nv_bfloat16* Vl = g_bf + OFF_AV_LO + ((size_t)bh << 17);

    // ---- stage Q tile (128x64 hi+lo) into stage-0 smem, then to registers ----
#pragma unroll
    for (int j = 0; j < 8; j++) {
        int c = tid + j * 256;
        int t = c >> 10;
        int r = (c >> 3) & 127;
        int cb = c & 7;
        uint32_t dst = sb + t * 16384 + r * 128 + ((cb ^ (r & 7)) << 4);
        const __nv_bfloat16* src = (t ? Ql : Qh) + (size_t)r * 64 + cb * 8;
        CP_ASYNC16(dst, src);
    }
    CP_COMMIT(); CP_WAIT(0);
    __syncthreads();

    uint32_t aQh[4][4], aQl[4][4];
    {
        int row = (wid << 4) + (lane & 7) + ((lane >> 3) & 1) * 8;
#pragma unroll
        for (int ks = 0; ks < 4; ks++) {
            int cb = ks * 2 + (lane >> 4);
            uint32_t ad = sb + row * 128 + ((cb ^ (row & 7)) << 4);
            LDSM4(aQh[ks], ad);
            LDSM4(aQl[ks], ad + 16384);
        }
    }
    __syncthreads();

    // ---- KV pipeline ----
    auto issue = [&](int kt, int stg) {
        const int k0 = kt << 6;
#pragma unroll
        for (int j = 0; j < 8; j++) {
            int c = tid + j * 256;
            int t = c >> 9;
            int r = (c >> 3) & 63;
            int cb = c & 7;
            uint32_t dst = sb + stg * ATT_STAGE + t * 8192 + r * 128 + ((cb ^ (r & 7)) << 4);
            const __nv_bfloat16* base = (t == 0) ? Kh : (t == 1) ? Kl : (t == 2) ? Vh : Vl;
            CP_ASYNC16(dst, base + (size_t)(k0 + r) * 64 + cb * 8);
        }
        CP_COMMIT();
    };
    issue(0, 0);
    issue(1, 1);
    issue(2, 2);

    float O[8][4];
#pragma unroll
    for (int f = 0; f < 8; f++)
#pragma unroll
        for (int e = 0; e < 4; e++) O[f][e] = 0.f;
    float l0 = 0.f, l1 = 0.f;
    const float cs = 0.125f * 1.4426950408889634f;

    const int krow = (lane & 7) + (lane >> 4) * 8;
    const int kcb  = (lane >> 3) & 1;
    const int vrow = (lane & 7) + ((lane >> 3) & 1) * 8;
    const int vcb  = lane >> 4;

    int stg = 0;  // kt % 3
    for (int kt = 0; kt < 32; kt++) {
        if (kt < 30) CP_WAIT(2);
        else if (kt == 30) CP_WAIT(1);
        else CP_WAIT(0);
        __syncthreads();
        const uint32_t st = sb + stg * ATT_STAGE;

        // two key-halves of 32 keys each: compute S-half, softmax, PV-half
#pragma unroll
        for (int h2 = 0; h2 < 2; h2++) {
            float S[4][4];
#pragma unroll
            for (int f = 0; f < 4; f++)
#pragma unroll
                for (int e = 0; e < 4; e++) S[f][e] = 0.f;

#pragma unroll
            for (int ks = 0; ks < 4; ks++) {
#pragma unroll
                for (int gg = 0; gg < 2; gg++) {
                    int g = 2 * h2 + gg;
                    int rr = g * 16 + krow;
                    int cb = ks * 2 + kcb;
                    uint32_t ad = st + rr * 128 + ((cb ^ (rr & 7)) << 4);
                    uint32_t KH[4], KL[4];
                    LDSM4(KH, ad);
                    LDSM4(KL, ad + 8192);
                    MMA16816(S[2 * gg],     aQh[ks], KH[0], KH[1]);
                    MMA16816(S[2 * gg],     aQh[ks], KL[0], KL[1]);
                    MMA16816(S[2 * gg],     aQl[ks], KH[0], KH[1]);
                    MMA16816(S[2 * gg + 1], aQh[ks], KH[2], KH[3]);
                    MMA16816(S[2 * gg + 1], aQh[ks], KL[2], KL[3]);
                    MMA16816(S[2 * gg + 1], aQl[ks], KH[2], KH[3]);
                }
            }

#pragma unroll
            for (int f = 0; f < 4; f++) {
#pragma unroll
                for (int e = 0; e < 4; e++) S[f][e] = ex2(S[f][e] * cs);
                l0 += S[f][0] + S[f][1];
                l1 += S[f][2] + S[f][3];
            }

#pragma unroll
            for (int jj = 0; jj < 2; jj++) {
                int kk = 2 * h2 + jj;
                uint32_t pH[4], pL[4];
                float* Sa = S[2 * jj];
                float* Sb = S[2 * jj + 1];
                pH[0] = packbf(Sa[0], Sa[1]);
                pH[1] = packbf(Sa[2], Sa[3]);
                pH[2] = packbf(Sb[0], Sb[1]);
                pH[3] = packbf(Sb[2], Sb[3]);
                pL[0] = packbf(Sa[0] - bflo(pH[0]), Sa[1] - bfhi(pH[0]));
                pL[1] = packbf(Sa[2] - bflo(pH[1]), Sa[3] - bfhi(pH[1]));
                pL[2] = packbf(Sb[0] - bflo(pH[2]), Sb[1] - bfhi(pH[2]));
                pL[3] = packbf(Sb[2] - bflo(pH[3]), Sb[3] - bfhi(pH[3]));
#pragma unroll
                for (int dp = 0; dp < 4; dp++) {
                    int rr = kk * 16 + vrow;
                    int cb = dp * 2 + vcb;
                    uint32_t ad = st + 16384 + rr * 128 + ((cb ^ (rr & 7)) << 4);
                    uint32_t VH[4], VL[4];
                    LDSM4T(VH, ad);
                    LDSM4T(VL, ad + 8192);
                    MMA16816(O[2 * dp],     pH, VH[0], VH[1]);
                    MMA16816(O[2 * dp],     pH, VL[0], VL[1]);
                    MMA16816(O[2 * dp],     pL, VH[0], VH[1]);
                    MMA16816(O[2 * dp + 1], pH, VH[2], VH[3]);
                    MMA16816(O[2 * dp + 1], pH, VL[2], VL[3]);
                    MMA16816(O[2 * dp + 1], pL, VH[2], VH[3]);
                }
            }
        }

        __syncthreads();
        if (kt + 3 < 32) issue(kt + 3, stg);   // tile kt+3 reuses stage kt%3
        stg = (stg == 2) ? 0 : stg + 1;
    }

    // ---- epilogue: normalize and write ctx as bf16 hi/lo [b,s,1024] ----
    l0 += __shfl_xor_sync(0xffffffffu, l0, 1);
    l0 += __shfl_xor_sync(0xffffffffu, l0, 2);
    l1 += __shfl_xor_sync(0xffffffffu, l1, 1);
    l1 += __shfl_xor_sync(0xffffffffu, l1, 2);
    const float inv0 = 1.f / l0;
    const float inv1 = 1.f / l1;

    const int b = bh >> 4, h = bh & 15;
    const int r0g = b * 2048 + q0 + (wid << 4) + (lane >> 2);
    __nv_bfloat16* ch = g_bf + OFF_CTX_HI;
    __nv_bfloat16* cl = g_bf + OFF_CTX_LO;
#pragma unroll
    for (int f = 0; f < 8; f++) {
        int col = (h << 6) + f * 8 + (lane & 3) * 2;
        split_store2(ch, cl, (size_t)r0g * 1024 + col,
                     O[f][0] * inv0, O[f][1] * inv0);
        split_store2(ch, cl, (size_t)(r0g + 8) * 1024 + col,
                     O[f][2] * inv1, O[f][3] * inv1);
    }
}

// ---------------------------------------------------------------------------
extern "C" void kernel_launch(void* const* d_in, const int* in_sizes, int n_in,
                              void* d_out, int out_size)
{
    const float* query = (const float*)d_in[0];
    const float* key   = (const float*)d_in[1];
    const float* value = (const float*)d_in[2];
    const float* Wq = (const float*)d_in[3];
    const float* bq = (const float*)d_in[4];
    const float* Wk = (const float*)d_in[5];
    const float* bk = (const float*)d_in[6];
    const float* Wv = (const float*)d_in[7];
    const float* bv = (const float*)d_in[8];
    const float* Wo = (const float*)d_in[9];
    const float* bo = (const float*)d_in[10];
    float* out = (float*)d_out;

    cudaFuncSetAttribute(gemm_qkv, cudaFuncAttributeMaxDynamicSharedMemorySize, GEMM_SMEM);
    cudaFuncSetAttribute(gemm_out, cudaFuncAttributeMaxDynamicSharedMemorySize, GEMM_SMEM);
    cudaFuncSetAttribute(attn_tc,  cudaFuncAttributeMaxDynamicSharedMemorySize, ATT_SMEM);

    convert_all<<<16384, 256>>>(query, key, value, Wq, Wk, Wv, Wo);

    gemm_qkv<<<dim3(DM / 128, MROWS / 128, 3), 512, GEMM_SMEM>>>(bq, bk, bv);

    attn_tc<<<dim3(SEQ / 128, BATCH * NH), 256, ATT_SMEM>>>();

    gemm_out<<<dim3(DM / 128, MROWS / 128), 512, GEMM_SMEM>>>(bo, out);
}